// round 13
// baseline (speedup 1.0000x reference)
#include <cuda_runtime.h>
#include <cuda_bf16.h>
#include <cuda_fp16.h>
#include <cstdint>
#include <cstdio>

constexpr int N_TOK = 4096;
constexpr int DIM = 256;
constexpr int NUM_LAYERS = 20;
constexpr int NUM_HEADS = 200;
constexpr int ND = N_TOK * DIM;
constexpr int WSZ = DIM * DIM;   // 65536

// ---------------- static device scratch (no cudaMalloc allowed) ----------------
__device__ __nv_bfloat16 g_xbf[ND];                                // x in bf16
__device__ __nv_bfloat16 g_Wb[(size_t)(3 * NUM_HEADS) * WSZ];      // Wq|Wk|Wv in bf16
__device__ uint16_t      g_QKV[(size_t)NUM_HEADS * 3 * ND];        // [head][q(f16)|k(f16)|v(bf16)]
__device__ __nv_bfloat16 g_O[(size_t)NUM_HEADS * ND];              // per-head attention out
__device__ float         g_h[2 * ND];                              // MLP ping-pong (fp32)

__device__ __forceinline__ float tanh_apx(float x) {
    float y; asm("tanh.approx.f32 %0, %1;" : "=f"(y) : "f"(x)); return y;
}
// p = e^u, u in [-0.5,0.5]; deg-4 Taylor (rel err ~1.6e-4, common-mode cancels in softmax)
__device__ __forceinline__ float exp_poly(float u) {
    float p = fmaf(u, 0.041666667f, 0.16666667f);
    p = fmaf(u, p, 0.5f);
    p = fmaf(u, p, 1.0f);
    p = fmaf(u, p, 1.0f);
    return p;
}
__device__ __forceinline__ float softp(float s) {
    return exp_poly(0.5f * tanh_apx(0.03125f * s));
}
__device__ __forceinline__ uint32_t smem_to_u32(const void* p) {
    uint32_t a;
    asm("{ .reg .u64 t; cvta.to.shared.u64 t, %1; cvt.u32.u64 %0, t; }" : "=r"(a) : "l"(p));
    return a;
}

// ---- baseline-PTX building blocks ----
__device__ __forceinline__ void mma16816(float* c, const uint32_t* a, uint32_t b0, uint32_t b1) {
    asm volatile(
        "mma.sync.aligned.m16n8k16.row.col.f32.bf16.bf16.f32 "
        "{%0,%1,%2,%3}, {%4,%5,%6,%7}, {%8,%9}, {%0,%1,%2,%3};"
        : "+f"(c[0]), "+f"(c[1]), "+f"(c[2]), "+f"(c[3])
        : "r"(a[0]), "r"(a[1]), "r"(a[2]), "r"(a[3]), "r"(b0), "r"(b1));
}
// fp16 in, fp16 accumulate (potential 2x rate)
__device__ __forceinline__ void mma16816h(uint32_t* d, const uint32_t* a, uint32_t b0, uint32_t b1) {
    asm volatile(
        "mma.sync.aligned.m16n8k16.row.col.f16.f16.f16.f16 "
        "{%0,%1}, {%2,%3,%4,%5}, {%6,%7}, {%0,%1};"
        : "+r"(d[0]), "+r"(d[1])
        : "r"(a[0]), "r"(a[1]), "r"(a[2]), "r"(a[3]), "r"(b0), "r"(b1));
}
__device__ __forceinline__ void ldsm4(uint32_t* r, uint32_t addr) {
    asm volatile("ldmatrix.sync.aligned.m8n8.x4.shared.b16 {%0,%1,%2,%3}, [%4];"
                 : "=r"(r[0]), "=r"(r[1]), "=r"(r[2]), "=r"(r[3]) : "r"(addr));
}
__device__ __forceinline__ void ldsm4t(uint32_t* r, uint32_t addr) {
    asm volatile("ldmatrix.sync.aligned.m8n8.x4.trans.shared.b16 {%0,%1,%2,%3}, [%4];"
                 : "=r"(r[0]), "=r"(r[1]), "=r"(r[2]), "=r"(r[3]) : "r"(addr));
}
#define CP_ASYNC16(dst, src) \
    asm volatile("cp.async.cg.shared.global [%0], [%1], 16;" :: "r"(dst), "l"(src))
#define CP_COMMIT() asm volatile("cp.async.commit_group;" ::: "memory")
#define CP_WAIT1() asm volatile("cp.async.wait_group 1;" ::: "memory")
#define CP_WAIT0() asm volatile("cp.async.wait_group 0;" ::: "memory")

// ---------------- prep: x fp32 -> bf16 ----------------
__global__ void prep_x(const float* __restrict__ x) {
    int i = blockIdx.x * blockDim.x + threadIdx.x;
    g_xbf[i] = __float2bfloat16(x[i]);
}

// ---------------- prep: Wq|Wk|Wv fp32 -> bf16 ----------------
__global__ void prep_w(const float* __restrict__ Wq, const float* __restrict__ Wk,
                       const float* __restrict__ Wv) {
    size_t i = (size_t)blockIdx.x * blockDim.x + threadIdx.x;
    float v;
    if (i < (size_t)200 * WSZ)        v = Wq[i];
    else if (i < (size_t)400 * WSZ)   v = Wk[i - (size_t)200 * WSZ];
    else                              v = Wv[i - (size_t)400 * WSZ];
    g_Wb[i] = __float2bfloat16(v);
}

// ---------------- projection GEMM: out[n][j0+0..63] = x[n][:] . W[j][:] + b ----------------
// grid (N_TOK/128, DIM/64, NUM_HEADS); block 256 (8 warps x 16 rows); 2 CTAs/SM.
// out_f16=1 -> fp16 output (Q,K); 0 -> bf16 (V).
constexpr int PJ_SMEM = 101376;   // As[128][264]bf16 (67584) + Bs[64][264]bf16 (33792)

__global__ __launch_bounds__(256, 2) void proj_kernel(
    const __nv_bfloat16* __restrict__ Wg, const float* __restrict__ bias,
    uint16_t* __restrict__ Cg, int out_f16) {
    extern __shared__ char sm[];
    __nv_bfloat16* As = (__nv_bfloat16*)sm;             // [128][264]
    __nv_bfloat16* Bs = (__nv_bfloat16*)(sm + 67584);   // [64][264]
    __shared__ float bias_s[64];
    const uint32_t sb = smem_to_u32(sm);

    const int tid = threadIdx.x, wid = tid >> 5, lane = tid & 31;
    const int n0 = blockIdx.x * 128, j0 = blockIdx.y * 64, z = blockIdx.z;
    const __nv_bfloat16* Wm = Wg + (size_t)z * WSZ + (size_t)j0 * DIM;

    if (tid < 64) bias_s[tid] = bias[z * DIM + j0 + tid];
    for (int t = tid; t < 4096; t += 256) {               // A tile 128x256
        int r = t >> 5, c = (t & 31) << 3;
        *(uint4*)&As[r * 264 + c] = *(const uint4*)&g_xbf[(size_t)(n0 + r) * DIM + c];
    }
    for (int t = tid; t < 2048; t += 256) {               // B strip 64x256
        int r = t >> 5, c = (t & 31) << 3;
        *(uint4*)&Bs[r * 264 + c] = *(const uint4*)&Wm[(size_t)r * DIM + c];
    }
    __syncthreads();

    const int wr = wid * 16;
    const uint32_t a_base = sb + (uint32_t)(wr + (lane & 15)) * 528 + ((lane >> 4) << 4);
    const uint32_t b_base = sb + 67584 +
        (uint32_t)((lane & 7) + ((lane >> 4) << 3)) * 528 + (((lane >> 3) & 1) << 4);

    float c[8][4];
#pragma unroll
    for (int i = 0; i < 8; i++)
#pragma unroll
        for (int j = 0; j < 4; j++) c[i][j] = 0.f;

#pragma unroll
    for (int kk = 0; kk < 16; kk++) {
        uint32_t a[4];
        ldsm4(a, a_base + kk * 32);
#pragma unroll
        for (int nq = 0; nq < 4; nq++) {
            uint32_t b[4];
            ldsm4(b, b_base + nq * (16 * 528) + kk * 32);
            mma16816(c[nq * 2], a, b[0], b[1]);
            mma16816(c[nq * 2 + 1], a, b[2], b[3]);
        }
    }

    const int row = n0 + wr + (lane >> 2);
    const int cl = (lane & 3) * 2;
    uint16_t* C0 = Cg + (size_t)z * 3 * ND + (size_t)row * DIM + j0;
    uint16_t* C1 = C0 + 8 * DIM;
#pragma unroll
    for (int nf = 0; nf < 8; nf++) {
        int col = nf * 8 + cl;
        float b0 = bias_s[col], b1 = bias_s[col + 1];
        float t0 = c[nf][0] + b0, t1 = c[nf][1] + b1;
        float t2 = c[nf][2] + b0, t3 = c[nf][3] + b1;
        uint32_t w0, w1;
        if (out_f16) {
            __half2 h0 = __floats2half2_rn(t0, t1), h1 = __floats2half2_rn(t2, t3);
            w0 = *(uint32_t*)&h0; w1 = *(uint32_t*)&h1;
        } else {
            __nv_bfloat162 h0 = __floats2bfloat162_rn(t0, t1), h1 = __floats2bfloat162_rn(t2, t3);
            w0 = *(uint32_t*)&h0; w1 = *(uint32_t*)&h1;
        }
        *(uint32_t*)&C0[col] = w0;
        *(uint32_t*)&C1[col] = w1;
    }
}

// ================= FA2-style fused flash attention =================
// BM=128 q rows/CTA, 8 warps x 16 rows, BN=64 keys/tile, full d=256 in regs.
// S-gemm: fp16 in / fp16 accum (Q,K fp16). PV: bf16 in / fp32 accum (V bf16).
constexpr int Q_OFF = 0;        // f16 [128][264]
constexpr int K_OFF = 67584;    // 2 stages x f16 [64][264]
constexpr int V_OFF = 135168;   // 2 stages x bf16 [64][264]
constexpr int KV_STAGE = 33792;
constexpr int ATTN_SMEM = 202752;

__global__ __launch_bounds__(256, 1) void attn_kernel() {
    extern __shared__ char sm[];
    const uint32_t sbase = smem_to_u32(sm);
    const int tid = threadIdx.x, wid = tid >> 5, lane = tid & 31;
    const int head = blockIdx.y;
    const int q0 = blockIdx.x * 128;
    const uint16_t* Qg = g_QKV + (size_t)(head * 3 + 0) * ND + (size_t)q0 * DIM;
    const uint16_t* Kg = g_QKV + (size_t)(head * 3 + 1) * ND;
    const uint16_t* Vg = g_QKV + (size_t)(head * 3 + 2) * ND;

    // Q -> smem (row-major, stride 264 halves)
    for (int t = tid; t < 4096; t += 256) {
        int r = t >> 5, c = (t & 31) << 3;
        *(uint4*)(sm + Q_OFF + (r * 264 + c) * 2) = *(const uint4*)&Qg[(size_t)r * DIM + c];
    }

    auto issueKV = [&](int kt, int stage) {
        const char* Ks = (const char*)(Kg + (size_t)kt * 64 * DIM);
        const char* Vs = (const char*)(Vg + (size_t)kt * 64 * DIM);
        uint32_t kd = sbase + K_OFF + stage * KV_STAGE;
        uint32_t vd = sbase + V_OFF + stage * KV_STAGE;
#pragma unroll
        for (int i = 0; i < 8; i++) {
            int t = tid + i * 256;
            int row = t >> 5, c = t & 31;
            uint32_t doff = row * 528 + c * 16;
            CP_ASYNC16(kd + doff, Ks + row * 512 + c * 16);
            CP_ASYNC16(vd + doff, Vs + row * 512 + c * 16);
        }
    };
    issueKV(0, 0); CP_COMMIT();
    issueKV(1, 1); CP_COMMIT();

    const int r0 = wid * 16;
    const uint32_t qa = sbase + Q_OFF + (uint32_t)(r0 + (lane & 15)) * 528 + ((lane >> 4) << 4);
    const uint32_t ka = (uint32_t)((lane & 7) + ((lane >> 4) << 3)) * 528 + (((lane >> 3) & 1) << 4);
    const uint32_t va = (uint32_t)((lane & 7) + (((lane >> 3) & 1) << 3)) * 528 + ((lane >> 4) << 4);

    float o[128];
#pragma unroll
    for (int i = 0; i < 128; i++) o[i] = 0.f;
    float rsum0 = 0.f, rsum1 = 0.f;

    for (int kt = 0; kt < 64; kt++) {
        if (kt < 63) { CP_WAIT1(); } else { CP_WAIT0(); }
        __syncthreads();
        const uint32_t Kst = sbase + K_OFF + (kt & 1) * KV_STAGE;
        const uint32_t Vst = sbase + V_OFF + (kt & 1) * KV_STAGE;

        // ---- S = Q @ K^T (16x64 per warp, K=256, fp16 accum) ----
        // sh[j*2], sh[j*2+1] : n8 block j, rows (r, r+8), 2 half cols each
        uint32_t sh[16];
#pragma unroll
        for (int i = 0; i < 16; i++) sh[i] = 0u;
#pragma unroll
        for (int kk = 0; kk < 16; kk++) {
            uint32_t a[4];
            ldsm4(a, qa + kk * 32);
#pragma unroll
            for (int np = 0; np < 4; np++) {
                uint32_t b[4];
                ldsm4(b, Kst + ka + np * 8448 + kk * 32);
                mma16816h(&sh[np * 4],     a, b[0], b[1]);
                mma16816h(&sh[np * 4 + 2], a, b[2], b[3]);
            }
        }
        // ---- softmax numerator + pack P (bf16) directly into A-fragment layout ----
        uint32_t pk[16];
#pragma unroll
        for (int j = 0; j < 8; j++) {
            __half2 ha = *(__half2*)&sh[j * 2];       // (row r, 2 cols)
            __half2 hb = *(__half2*)&sh[j * 2 + 1];   // (row r+8, 2 cols)
            float p00 = softp(__low2float(ha)), p01 = softp(__high2float(ha));
            float p10 = softp(__low2float(hb)), p11 = softp(__high2float(hb));
            rsum0 += p00 + p01; rsum1 += p10 + p11;
            __nv_bfloat162 q0h = __floats2bfloat162_rn(p00, p01);
            __nv_bfloat162 q1h = __floats2bfloat162_rn(p10, p11);
            int base = (j >> 1) * 4 + (j & 1) * 2;
            pk[base]     = *(uint32_t*)&q0h;
            pk[base + 1] = *(uint32_t*)&q1h;
        }
        // ---- O += P @ V (16x256 per warp, k=64, fp32 accum) ----
#pragma unroll
        for (int kk = 0; kk < 4; kk++) {
#pragma unroll
            for (int np = 0; np < 16; np++) {
                uint32_t b[4];
                ldsm4t(b, Vst + va + kk * 8448 + np * 32);
                mma16816(&o[np * 8], &pk[kk * 4], b[0], b[1]);
                mma16816(&o[np * 8 + 4], &pk[kk * 4], b[2], b[3]);
            }
        }
        if (kt < 62) {
            __syncthreads();
            issueKV(kt + 2, kt & 1);
            CP_COMMIT();
        }
    }

    // ---- finalize: complete row sums across the quad, normalize, store bf16 ----
    rsum0 += __shfl_xor_sync(0xffffffffu, rsum0, 1);
    rsum0 += __shfl_xor_sync(0xffffffffu, rsum0, 2);
    rsum1 += __shfl_xor_sync(0xffffffffu, rsum1, 1);
    rsum1 += __shfl_xor_sync(0xffffffffu, rsum1, 2);
    float inv0 = 1.0f / rsum0, inv1 = 1.0f / rsum1;

    const int row = q0 + r0 + (lane >> 2);
    const int colb = (lane & 3) * 2;
    __nv_bfloat16* O0 = g_O + (size_t)head * ND + (size_t)row * DIM;
    __nv_bfloat16* O1 = O0 + 8 * DIM;
#pragma unroll
    for (int n = 0; n < 32; n++) {
        *(__nv_bfloat162*)&O0[n * 8 + colb] =
            __floats2bfloat162_rn(o[n * 4 + 0] * inv0, o[n * 4 + 1] * inv0);
        *(__nv_bfloat162*)&O1[n * 8 + colb] =
            __floats2bfloat162_rn(o[n * 4 + 2] * inv1, o[n * 4 + 3] * inv1);
    }
}

// ---------------- mean over heads (deterministic, no atomics) -> fp32 ----------------
__global__ void reduce_kernel(float* __restrict__ out) {
    int i = blockIdx.x * blockDim.x + threadIdx.x;
    const __nv_bfloat16* p = g_O + i;
    float s = 0.f;
#pragma unroll 8
    for (int h = 0; h < NUM_HEADS; h++) s += __bfloat162float(p[(size_t)h * ND]);
    out[i] = s * (1.0f / NUM_HEADS);
}

// ---------------- fp32 GEMM for MLP/final (precision-critical path) ----------------
__global__ __launch_bounds__(256) void gemm_fp32(
    const float* __restrict__ A, const float* __restrict__ B,
    const float* __restrict__ bias, float* __restrict__ C,
    int transB, int mode) {
    __shared__ float As[16][68];
    __shared__ float Bs[16][68];
    const int tid = threadIdx.x;
    const int n0 = blockIdx.x * 64;
    const int j0 = blockIdx.y * 64;
    const int r0 = (tid >> 4) * 4;
    const int c0 = (tid & 15) * 4;
    float acc[4][4];
#pragma unroll
    for (int i = 0; i < 4; i++)
#pragma unroll
        for (int j = 0; j < 4; j++) acc[i][j] = 0.f;

    for (int ko = 0; ko < DIM; ko += 16) {
        __syncthreads();
        {
            int k = tid & 15, n = tid >> 4;
#pragma unroll
            for (int p = 0; p < 4; p++)
                As[k][n + 16 * p] = A[(size_t)(n0 + n + 16 * p) * DIM + ko + k];
            if (transB) {
#pragma unroll
                for (int p = 0; p < 4; p++)
                    Bs[k][n + 16 * p] = B[(size_t)(j0 + n + 16 * p) * DIM + ko + k];
            } else {
                int j = tid & 63, kq = tid >> 6;
#pragma unroll
                for (int p = 0; p < 4; p++)
                    Bs[kq + 4 * p][j] = B[(size_t)(ko + kq + 4 * p) * DIM + j0 + j];
            }
        }
        __syncthreads();
#pragma unroll
        for (int kk = 0; kk < 16; kk++) {
            float4 a = *(const float4*)&As[kk][r0];
            float4 b = *(const float4*)&Bs[kk][c0];
            float av[4] = {a.x, a.y, a.z, a.w};
            float bv[4] = {b.x, b.y, b.z, b.w};
#pragma unroll
            for (int i = 0; i < 4; i++)
#pragma unroll
                for (int j = 0; j < 4; j++) acc[i][j] += av[i] * bv[j];
        }
    }
#pragma unroll
    for (int i = 0; i < 4; i++) {
        int n = n0 + r0 + i;
        float4 v;
        float* vp = &v.x;
#pragma unroll
        for (int j = 0; j < 4; j++) {
            int cidx = j0 + c0 + j;
            float t = acc[i][j];
            if (mode == 0) { t += bias[cidx]; t = t > 0.f ? t : 0.f; }
            else           { t = 1.f / (1.f + expf(-t)) + bias[cidx]; }
            vp[j] = t;
        }
        *(float4*)&C[(size_t)n * DIM + j0 + c0] = v;
    }
}

// ---------------- launch ----------------
extern "C" void kernel_launch(void* const* d_in, const int* in_sizes, int n_in,
                              void* d_out, int out_size) {
    const float* x  = (const float*)d_in[0];
    const float* Wq = (const float*)d_in[1];
    const float* bq = (const float*)d_in[2];
    const float* Wk = (const float*)d_in[3];
    const float* bk = (const float*)d_in[4];
    const float* Wv = (const float*)d_in[5];
    const float* bv = (const float*)d_in[6];
    const float* Wl = (const float*)d_in[7];
    const float* bl = (const float*)d_in[8];
    const float* fw = (const float*)d_in[9];
    const float* fb = (const float*)d_in[10];

    cudaFuncSetAttribute(proj_kernel, cudaFuncAttributeMaxDynamicSharedMemorySize, PJ_SMEM);
    cudaFuncSetAttribute(attn_kernel, cudaFuncAttributeMaxDynamicSharedMemorySize, ATTN_SMEM);

    __nv_bfloat16* wb = nullptr;  cudaGetSymbolAddress((void**)&wb, g_Wb);
    uint16_t* qkv = nullptr;      cudaGetSymbolAddress((void**)&qkv, g_QKV);
    float* hbuf = nullptr;        cudaGetSymbolAddress((void**)&hbuf, g_h);

    // launches #0,#1
    prep_x<<<ND / 256, 256>>>(x);
    prep_w<<<(int)(((size_t)600 * WSZ) / 256), 256>>>(Wq, Wk, Wv);

    // launches #2,#3,#4: Q/K/V projections (Q,K fp16; V bf16)
    proj_kernel<<<dim3(N_TOK / 128, DIM / 64, NUM_HEADS), 256, PJ_SMEM>>>(
        wb + (size_t)0 * NUM_HEADS * WSZ, bq, qkv + (size_t)0 * ND, 1);
    proj_kernel<<<dim3(N_TOK / 128, DIM / 64, NUM_HEADS), 256, PJ_SMEM>>>(
        wb + (size_t)1 * NUM_HEADS * WSZ, bk, qkv + (size_t)1 * ND, 1);
    proj_kernel<<<dim3(N_TOK / 128, DIM / 64, NUM_HEADS), 256, PJ_SMEM>>>(
        wb + (size_t)2 * NUM_HEADS * WSZ, bv, qkv + (size_t)2 * ND, 0);

    // launch #5 (ncu -s 5 -c 1 captures this one)
    attn_kernel<<<dim3(N_TOK / 128, NUM_HEADS), 256, ATTN_SMEM>>>();

    reduce_kernel<<<ND / 256, 256>>>(hbuf);

    for (int l = 0; l < NUM_LAYERS; l++) {
        gemm_fp32<<<dim3(N_TOK / 64, DIM / 64), 256>>>(
            hbuf + (size_t)(l & 1) * ND, Wl + (size_t)l * WSZ, bl + (size_t)l * DIM,
            hbuf + (size_t)((l + 1) & 1) * ND, 1, 0);
    }
    gemm_fp32<<<dim3(N_TOK / 64, DIM / 64), 256>>>(hbuf, fw, fb, (float*)d_out, 0, 1);
}

// round 16
// speedup vs baseline: 1.1241x; 1.1241x over previous
#include <cuda_runtime.h>
#include <cuda_bf16.h>
#include <cuda_fp16.h>
#include <cstdint>
#include <cstdio>

constexpr int N_TOK = 4096;
constexpr int DIM = 256;
constexpr int NUM_LAYERS = 20;
constexpr int NUM_HEADS = 200;
constexpr int ND = N_TOK * DIM;
constexpr int WSZ = DIM * DIM;   // 65536

// ---------------- static device scratch (no cudaMalloc allowed) ----------------
__device__ __nv_bfloat16 g_xbf[ND];                                // x in bf16
__device__ __nv_bfloat16 g_Wb[(size_t)(3 * NUM_HEADS) * WSZ];      // Wq|Wk|Wv in bf16
__device__ uint16_t      g_QKV[(size_t)NUM_HEADS * 3 * ND];        // [head][q(f16)|k(f16)|v(bf16)]
__device__ __nv_bfloat16 g_O[(size_t)NUM_HEADS * ND];              // per-head attention out
__device__ float         g_h[2 * ND];                              // MLP ping-pong (fp32)

__device__ __forceinline__ float tanh_apx(float x) {
    float y; asm("tanh.approx.f32 %0, %1;" : "=f"(y) : "f"(x)); return y;
}
// p = e^u, u in [-0.5,0.5]; deg-4 Taylor (rel err ~1.6e-4, common-mode cancels in softmax)
__device__ __forceinline__ float exp_poly(float u) {
    float p = fmaf(u, 0.041666667f, 0.16666667f);
    p = fmaf(u, p, 0.5f);
    p = fmaf(u, p, 1.0f);
    p = fmaf(u, p, 1.0f);
    return p;
}
__device__ __forceinline__ float softp(float s) {
    return exp_poly(0.5f * tanh_apx(0.03125f * s));
}
__device__ __forceinline__ uint32_t smem_to_u32(const void* p) {
    uint32_t a;
    asm("{ .reg .u64 t; cvta.to.shared.u64 t, %1; cvt.u32.u64 %0, t; }" : "=r"(a) : "l"(p));
    return a;
}

// ---- baseline-PTX building blocks ----
__device__ __forceinline__ void mma16816(float* c, const uint32_t* a, uint32_t b0, uint32_t b1) {
    asm volatile(
        "mma.sync.aligned.m16n8k16.row.col.f32.bf16.bf16.f32 "
        "{%0,%1,%2,%3}, {%4,%5,%6,%7}, {%8,%9}, {%0,%1,%2,%3};"
        : "+f"(c[0]), "+f"(c[1]), "+f"(c[2]), "+f"(c[3])
        : "r"(a[0]), "r"(a[1]), "r"(a[2]), "r"(a[3]), "r"(b0), "r"(b1));
}
// fp16 in, fp16 accumulate
__device__ __forceinline__ void mma16816h(uint32_t* d, const uint32_t* a, uint32_t b0, uint32_t b1) {
    asm volatile(
        "mma.sync.aligned.m16n8k16.row.col.f16.f16.f16.f16 "
        "{%0,%1}, {%2,%3,%4,%5}, {%6,%7}, {%0,%1};"
        : "+r"(d[0]), "+r"(d[1])
        : "r"(a[0]), "r"(a[1]), "r"(a[2]), "r"(a[3]), "r"(b0), "r"(b1));
}
__device__ __forceinline__ void ldsm4(uint32_t* r, uint32_t addr) {
    asm volatile("ldmatrix.sync.aligned.m8n8.x4.shared.b16 {%0,%1,%2,%3}, [%4];"
                 : "=r"(r[0]), "=r"(r[1]), "=r"(r[2]), "=r"(r[3]) : "r"(addr));
}
__device__ __forceinline__ void ldsm4t(uint32_t* r, uint32_t addr) {
    asm volatile("ldmatrix.sync.aligned.m8n8.x4.trans.shared.b16 {%0,%1,%2,%3}, [%4];"
                 : "=r"(r[0]), "=r"(r[1]), "=r"(r[2]), "=r"(r[3]) : "r"(addr));
}
#define CP_ASYNC16(dst, src) \
    asm volatile("cp.async.cg.shared.global [%0], [%1], 16;" :: "r"(dst), "l"(src))
#define CP_COMMIT() asm volatile("cp.async.commit_group;" ::: "memory")
#define CP_WAIT2() asm volatile("cp.async.wait_group 2;" ::: "memory")
#define CP_WAIT1() asm volatile("cp.async.wait_group 1;" ::: "memory")
#define CP_WAIT0() asm volatile("cp.async.wait_group 0;" ::: "memory")

// ---------------- prep: x fp32 -> bf16 ----------------
__global__ void prep_x(const float* __restrict__ x) {
    int i = blockIdx.x * blockDim.x + threadIdx.x;
    g_xbf[i] = __float2bfloat16(x[i]);
}

// ---------------- prep: Wq|Wk|Wv fp32 -> bf16 ----------------
__global__ void prep_w(const float* __restrict__ Wq, const float* __restrict__ Wk,
                       const float* __restrict__ Wv) {
    size_t i = (size_t)blockIdx.x * blockDim.x + threadIdx.x;
    float v;
    if (i < (size_t)200 * WSZ)        v = Wq[i];
    else if (i < (size_t)400 * WSZ)   v = Wk[i - (size_t)200 * WSZ];
    else                              v = Wv[i - (size_t)400 * WSZ];
    g_Wb[i] = __float2bfloat16(v);
}

// ---------------- projection GEMM (cp.async k-pipelined) ----------------
// C[n][j] = x[n][:] . W[j][:] + b ; BM=128, BN=128, k-chunks of 64, 3-stage pipeline.
// grid (N_TOK/128, DIM/128, NUM_HEADS); block 256 (8 warps = 4m x 2n); 2 CTAs/SM.
// out_f16=1 -> fp16 output (Q,K); 0 -> bf16 (V).
constexpr int PJ_B_OFF = 18432;          // within stage: A [128][144B] then B [128][144B]
constexpr int PJ_STAGE = 36864;
constexpr int PJ_SMEM = 3 * PJ_STAGE;    // 110592 -> 2 CTAs/SM

__global__ __launch_bounds__(256, 2) void proj_kernel(
    const __nv_bfloat16* __restrict__ Wg, const float* __restrict__ bias,
    uint16_t* __restrict__ Cg, int out_f16) {
    extern __shared__ char sm[];
    const uint32_t sb = smem_to_u32(sm);
    __shared__ float bias_s[128];

    const int tid = threadIdx.x, wid = tid >> 5, lane = tid & 31;
    const int n0 = blockIdx.x * 128, j0 = blockIdx.y * 128, z = blockIdx.z;
    const __nv_bfloat16* Wm = Wg + (size_t)z * WSZ;

    if (tid < 128) bias_s[tid] = bias[z * DIM + j0 + tid];

    // issue one k-chunk (A 128x128B + B 128x128B) into stage stg
    auto issue = [&](int ck, int stg) {
        const __nv_bfloat16* Asrc = g_xbf + (size_t)n0 * DIM + ck * 64;
        const __nv_bfloat16* Bsrc = Wm + (size_t)j0 * DIM + ck * 64;
        uint32_t ab = sb + stg * PJ_STAGE;
#pragma unroll
        for (int i = 0; i < 4; i++) {
            int idx = tid + i * 256;
            int row = idx >> 3, c = idx & 7;
            CP_ASYNC16(ab + row * 144 + c * 16,
                       (const char*)(Asrc + (size_t)row * DIM + c * 8));
            CP_ASYNC16(ab + PJ_B_OFF + row * 144 + c * 16,
                       (const char*)(Bsrc + (size_t)row * DIM + c * 8));
        }
        CP_COMMIT();
    };

    const int wr = (wid & 3) * 32;     // m offset (32 rows per warp)
    const int wn = (wid >> 2) * 64;    // n offset (64 cols per warp)
    float c[2][8][4];
#pragma unroll
    for (int i = 0; i < 2; i++)
#pragma unroll
        for (int j = 0; j < 8; j++)
#pragma unroll
            for (int k = 0; k < 4; k++) c[i][j][k] = 0.f;

    auto comp = [&](int stg) {
        uint32_t sA = sb + stg * PJ_STAGE;
        uint32_t aaddr = sA + (uint32_t)(wr + (lane & 15)) * 144 + ((lane >> 4) << 4);
        uint32_t baddr = sA + PJ_B_OFF +
            (uint32_t)(wn + (lane & 7) + ((lane >> 4) << 3)) * 144 + (((lane >> 3) & 1) << 4);
#pragma unroll
        for (int kk = 0; kk < 4; kk++) {
            uint32_t a0[4], a1[4];
            ldsm4(a0, aaddr + kk * 32);
            ldsm4(a1, aaddr + 16 * 144 + kk * 32);
#pragma unroll
            for (int nq = 0; nq < 4; nq++) {
                uint32_t b[4];
                ldsm4(b, baddr + nq * (16 * 144) + kk * 32);
                mma16816(c[0][nq * 2],     a0, b[0], b[1]);
                mma16816(c[0][nq * 2 + 1], a0, b[2], b[3]);
                mma16816(c[1][nq * 2],     a1, b[0], b[1]);
                mma16816(c[1][nq * 2 + 1], a1, b[2], b[3]);
            }
        }
    };

    issue(0, 0); issue(1, 1); issue(2, 2);
    CP_WAIT2(); __syncthreads();
    comp(0);
    __syncthreads();          // all warps done reading stage 0 before refill
    issue(3, 0);
    CP_WAIT2(); __syncthreads();
    comp(1);
    CP_WAIT1(); __syncthreads();
    comp(2);
    CP_WAIT0(); __syncthreads();
    comp(0);                  // chunk 3 lives in stage 0 (refilled)

    // epilogue: bias + pack + store
    const int rq = lane >> 2, cl = (lane & 3) * 2;
#pragma unroll
    for (int mi = 0; mi < 2; mi++) {
        int row = n0 + wr + mi * 16 + rq;
        uint16_t* C0 = Cg + (size_t)z * 3 * ND + (size_t)row * DIM + j0;
        uint16_t* C1 = C0 + 8 * DIM;
#pragma unroll
        for (int nf = 0; nf < 8; nf++) {
            int bcol = wn + nf * 8 + cl;
            float b0 = bias_s[bcol], b1 = bias_s[bcol + 1];
            float t0 = c[mi][nf][0] + b0, t1 = c[mi][nf][1] + b1;
            float t2 = c[mi][nf][2] + b0, t3 = c[mi][nf][3] + b1;
            uint32_t w0, w1;
            if (out_f16) {
                __half2 h0 = __floats2half2_rn(t0, t1), h1 = __floats2half2_rn(t2, t3);
                w0 = *(uint32_t*)&h0; w1 = *(uint32_t*)&h1;
            } else {
                __nv_bfloat162 h0 = __floats2bfloat162_rn(t0, t1), h1 = __floats2bfloat162_rn(t2, t3);
                w0 = *(uint32_t*)&h0; w1 = *(uint32_t*)&h1;
            }
            *(uint32_t*)&C0[bcol] = w0;
            *(uint32_t*)&C1[bcol] = w1;
        }
    }
}

// ================= FA2-style fused flash attention =================
// BM=128 q rows/CTA, 8 warps x 16 rows, BN=64 keys/tile, full d=256 in regs.
// S-gemm: fp16 in / fp16 accum (Q,K fp16). PV: bf16 in / fp32 accum (V bf16).
constexpr int Q_OFF = 0;        // f16 [128][264]
constexpr int K_OFF = 67584;    // 2 stages x f16 [64][264]
constexpr int V_OFF = 135168;   // 2 stages x bf16 [64][264]
constexpr int KV_STAGE = 33792;
constexpr int ATTN_SMEM = 202752;

__global__ __launch_bounds__(256, 1) void attn_kernel() {
    extern __shared__ char sm[];
    const uint32_t sbase = smem_to_u32(sm);
    const int tid = threadIdx.x, wid = tid >> 5, lane = tid & 31;
    const int head = blockIdx.y;
    const int q0 = blockIdx.x * 128;
    const uint16_t* Qg = g_QKV + (size_t)(head * 3 + 0) * ND + (size_t)q0 * DIM;
    const uint16_t* Kg = g_QKV + (size_t)(head * 3 + 1) * ND;
    const uint16_t* Vg = g_QKV + (size_t)(head * 3 + 2) * ND;

    // Q -> smem (row-major, stride 264 halves)
    for (int t = tid; t < 4096; t += 256) {
        int r = t >> 5, c = (t & 31) << 3;
        *(uint4*)(sm + Q_OFF + (r * 264 + c) * 2) = *(const uint4*)&Qg[(size_t)r * DIM + c];
    }

    auto issueKV = [&](int kt, int stage) {
        const char* Ks = (const char*)(Kg + (size_t)kt * 64 * DIM);
        const char* Vs = (const char*)(Vg + (size_t)kt * 64 * DIM);
        uint32_t kd = sbase + K_OFF + stage * KV_STAGE;
        uint32_t vd = sbase + V_OFF + stage * KV_STAGE;
#pragma unroll
        for (int i = 0; i < 8; i++) {
            int t = tid + i * 256;
            int row = t >> 5, c = t & 31;
            uint32_t doff = row * 528 + c * 16;
            CP_ASYNC16(kd + doff, Ks + row * 512 + c * 16);
            CP_ASYNC16(vd + doff, Vs + row * 512 + c * 16);
        }
    };
    issueKV(0, 0); CP_COMMIT();
    issueKV(1, 1); CP_COMMIT();

    const int r0 = wid * 16;
    const uint32_t qa = sbase + Q_OFF + (uint32_t)(r0 + (lane & 15)) * 528 + ((lane >> 4) << 4);
    const uint32_t ka = (uint32_t)((lane & 7) + ((lane >> 4) << 3)) * 528 + (((lane >> 3) & 1) << 4);
    const uint32_t va = (uint32_t)((lane & 7) + (((lane >> 3) & 1) << 3)) * 528 + ((lane >> 4) << 4);

    float o[128];
#pragma unroll
    for (int i = 0; i < 128; i++) o[i] = 0.f;
    float rsum0 = 0.f, rsum1 = 0.f;

    for (int kt = 0; kt < 64; kt++) {
        if (kt < 63) { CP_WAIT1(); } else { CP_WAIT0(); }
        __syncthreads();
        const uint32_t Kst = sbase + K_OFF + (kt & 1) * KV_STAGE;
        const uint32_t Vst = sbase + V_OFF + (kt & 1) * KV_STAGE;

        // ---- S = Q @ K^T (16x64 per warp, K=256, fp16 accum) ----
        uint32_t sh[16];
#pragma unroll
        for (int i = 0; i < 16; i++) sh[i] = 0u;
#pragma unroll
        for (int kk = 0; kk < 16; kk++) {
            uint32_t a[4];
            ldsm4(a, qa + kk * 32);
#pragma unroll
            for (int np = 0; np < 4; np++) {
                uint32_t b[4];
                ldsm4(b, Kst + ka + np * 8448 + kk * 32);
                mma16816h(&sh[np * 4],     a, b[0], b[1]);
                mma16816h(&sh[np * 4 + 2], a, b[2], b[3]);
            }
        }
        // ---- softmax numerator + pack P (bf16) directly into A-fragment layout ----
        uint32_t pk[16];
#pragma unroll
        for (int j = 0; j < 8; j++) {
            __half2 ha = *(__half2*)&sh[j * 2];       // (row r, 2 cols)
            __half2 hb = *(__half2*)&sh[j * 2 + 1];   // (row r+8, 2 cols)
            float p00 = softp(__low2float(ha)), p01 = softp(__high2float(ha));
            float p10 = softp(__low2float(hb)), p11 = softp(__high2float(hb));
            rsum0 += p00 + p01; rsum1 += p10 + p11;
            __nv_bfloat162 q0h = __floats2bfloat162_rn(p00, p01);
            __nv_bfloat162 q1h = __floats2bfloat162_rn(p10, p11);
            int base = (j >> 1) * 4 + (j & 1) * 2;
            pk[base]     = *(uint32_t*)&q0h;
            pk[base + 1] = *(uint32_t*)&q1h;
        }
        // ---- O += P @ V (16x256 per warp, k=64, fp32 accum) ----
#pragma unroll
        for (int kk = 0; kk < 4; kk++) {
#pragma unroll
            for (int np = 0; np < 16; np++) {
                uint32_t b[4];
                ldsm4t(b, Vst + va + kk * 8448 + np * 32);
                mma16816(&o[np * 8], &pk[kk * 4], b[0], b[1]);
                mma16816(&o[np * 8 + 4], &pk[kk * 4], b[2], b[3]);
            }
        }
        if (kt < 62) {
            __syncthreads();
            issueKV(kt + 2, kt & 1);
            CP_COMMIT();
        }
    }

    // ---- finalize: complete row sums across the quad, normalize, store bf16 ----
    rsum0 += __shfl_xor_sync(0xffffffffu, rsum0, 1);
    rsum0 += __shfl_xor_sync(0xffffffffu, rsum0, 2);
    rsum1 += __shfl_xor_sync(0xffffffffu, rsum1, 1);
    rsum1 += __shfl_xor_sync(0xffffffffu, rsum1, 2);
    float inv0 = 1.0f / rsum0, inv1 = 1.0f / rsum1;

    const int row = q0 + r0 + (lane >> 2);
    const int colb = (lane & 3) * 2;
    __nv_bfloat16* O0 = g_O + (size_t)head * ND + (size_t)row * DIM;
    __nv_bfloat16* O1 = O0 + 8 * DIM;
#pragma unroll
    for (int n = 0; n < 32; n++) {
        *(__nv_bfloat162*)&O0[n * 8 + colb] =
            __floats2bfloat162_rn(o[n * 4 + 0] * inv0, o[n * 4 + 1] * inv0);
        *(__nv_bfloat162*)&O1[n * 8 + colb] =
            __floats2bfloat162_rn(o[n * 4 + 2] * inv1, o[n * 4 + 3] * inv1);
    }
}

// ---------------- mean over heads (deterministic, no atomics) -> fp32 ----------------
__global__ void reduce_kernel(float* __restrict__ out) {
    int i = blockIdx.x * blockDim.x + threadIdx.x;
    const __nv_bfloat16* p = g_O + i;
    float s = 0.f;
#pragma unroll 8
    for (int h = 0; h < NUM_HEADS; h++) s += __bfloat162float(p[(size_t)h * ND]);
    out[i] = s * (1.0f / NUM_HEADS);
}

// ---------------- fp32 GEMM for MLP/final (precision-critical path) ----------------
__global__ __launch_bounds__(256) void gemm_fp32(
    const float* __restrict__ A, const float* __restrict__ B,
    const float* __restrict__ bias, float* __restrict__ C,
    int transB, int mode) {
    __shared__ float As[16][68];
    __shared__ float Bs[16][68];
    const int tid = threadIdx.x;
    const int n0 = blockIdx.x * 64;
    const int j0 = blockIdx.y * 64;
    const int r0 = (tid >> 4) * 4;
    const int c0 = (tid & 15) * 4;
    float acc[4][4];
#pragma unroll
    for (int i = 0; i < 4; i++)
#pragma unroll
        for (int j = 0; j < 4; j++) acc[i][j] = 0.f;

    for (int ko = 0; ko < DIM; ko += 16) {
        __syncthreads();
        {
            int k = tid & 15, n = tid >> 4;
#pragma unroll
            for (int p = 0; p < 4; p++)
                As[k][n + 16 * p] = A[(size_t)(n0 + n + 16 * p) * DIM + ko + k];
            if (transB) {
#pragma unroll
                for (int p = 0; p < 4; p++)
                    Bs[k][n + 16 * p] = B[(size_t)(j0 + n + 16 * p) * DIM + ko + k];
            } else {
                int j = tid & 63, kq = tid >> 6;
#pragma unroll
                for (int p = 0; p < 4; p++)
                    Bs[kq + 4 * p][j] = B[(size_t)(ko + kq + 4 * p) * DIM + j0 + j];
            }
        }
        __syncthreads();
#pragma unroll
        for (int kk = 0; kk < 16; kk++) {
            float4 a = *(const float4*)&As[kk][r0];
            float4 b = *(const float4*)&Bs[kk][c0];
            float av[4] = {a.x, a.y, a.z, a.w};
            float bv[4] = {b.x, b.y, b.z, b.w};
#pragma unroll
            for (int i = 0; i < 4; i++)
#pragma unroll
                for (int j = 0; j < 4; j++) acc[i][j] += av[i] * bv[j];
        }
    }
#pragma unroll
    for (int i = 0; i < 4; i++) {
        int n = n0 + r0 + i;
        float4 v;
        float* vp = &v.x;
#pragma unroll
        for (int j = 0; j < 4; j++) {
            int cidx = j0 + c0 + j;
            float t = acc[i][j];
            if (mode == 0) { t += bias[cidx]; t = t > 0.f ? t : 0.f; }
            else           { t = 1.f / (1.f + expf(-t)) + bias[cidx]; }
            vp[j] = t;
        }
        *(float4*)&C[(size_t)n * DIM + j0 + c0] = v;
    }
}

// ---------------- launch ----------------
extern "C" void kernel_launch(void* const* d_in, const int* in_sizes, int n_in,
                              void* d_out, int out_size) {
    const float* x  = (const float*)d_in[0];
    const float* Wq = (const float*)d_in[1];
    const float* bq = (const float*)d_in[2];
    const float* Wk = (const float*)d_in[3];
    const float* bk = (const float*)d_in[4];
    const float* Wv = (const float*)d_in[5];
    const float* bv = (const float*)d_in[6];
    const float* Wl = (const float*)d_in[7];
    const float* bl = (const float*)d_in[8];
    const float* fw = (const float*)d_in[9];
    const float* fb = (const float*)d_in[10];

    cudaFuncSetAttribute(proj_kernel, cudaFuncAttributeMaxDynamicSharedMemorySize, PJ_SMEM);
    cudaFuncSetAttribute(attn_kernel, cudaFuncAttributeMaxDynamicSharedMemorySize, ATTN_SMEM);

    __nv_bfloat16* wb = nullptr;  cudaGetSymbolAddress((void**)&wb, g_Wb);
    uint16_t* qkv = nullptr;      cudaGetSymbolAddress((void**)&qkv, g_QKV);
    float* hbuf = nullptr;        cudaGetSymbolAddress((void**)&hbuf, g_h);

    // launches #0,#1
    prep_x<<<ND / 256, 256>>>(x);
    prep_w<<<(int)(((size_t)600 * WSZ) / 256), 256>>>(Wq, Wk, Wv);

    // launches #2,#3,#4: Q/K/V projections (Q,K fp16; V bf16)
    proj_kernel<<<dim3(N_TOK / 128, DIM / 128, NUM_HEADS), 256, PJ_SMEM>>>(
        wb + (size_t)0 * NUM_HEADS * WSZ, bq, qkv + (size_t)0 * ND, 1);
    proj_kernel<<<dim3(N_TOK / 128, DIM / 128, NUM_HEADS), 256, PJ_SMEM>>>(
        wb + (size_t)1 * NUM_HEADS * WSZ, bk, qkv + (size_t)1 * ND, 1);
    proj_kernel<<<dim3(N_TOK / 128, DIM / 128, NUM_HEADS), 256, PJ_SMEM>>>(
        wb + (size_t)2 * NUM_HEADS * WSZ, bv, qkv + (size_t)2 * ND, 0);

    // launch #5 (ncu -s 5 -c 1 captures this one)
    attn_kernel<<<dim3(N_TOK / 128, NUM_HEADS), 256, ATTN_SMEM>>>();

    reduce_kernel<<<ND / 256, 256>>>(hbuf);

    for (int l = 0; l < NUM_LAYERS; l++) {
        gemm_fp32<<<dim3(N_TOK / 64, DIM / 64), 256>>>(
            hbuf + (size_t)(l & 1) * ND, Wl + (size_t)l * WSZ, bl + (size_t)l * DIM,
            hbuf + (size_t)((l + 1) & 1) * ND, 1, 0);
    }
    gemm_fp32<<<dim3(N_TOK / 64, DIM / 64), 256>>>(hbuf, fw, fb, (float*)d_out, 0, 1);
}